// round 12
// baseline (speedup 1.0000x reference)
#include <cuda_runtime.h>

// Fused Canny front-end. Reference's NMS/orientation path is dead code.
//
// v7 (interior CTAs): full separable factorization
//   gx = corrV(w7, corrH(d7, img)),  gy = corrV(d7, corrH(w7, img))
//   w7 = conv([1,2,1], g5)  (symmetric: w0..w3),  d7 = conv([1,0,-1], g5)
//   (antisymmetric, d3 = g3-g1 = 0 exactly).
// Stage A: two packed 7-tap horizontal filters -> sGX/sGY (aligned f4 grid).
// Stage B: two pure vertical 7-tap convolutions on own column, f32x2.
// Border CTAs (30%) use the v6 body (blurred-tensor zero-pad semantics exact).

typedef unsigned long long u64;

__device__ __forceinline__ u64 pk2(float lo, float hi) {
    u64 r; asm("mov.b64 %0, {%1, %2};" : "=l"(r) : "f"(lo), "f"(hi)); return r;
}
__device__ __forceinline__ void upk2(u64 v, float& lo, float& hi) {
    asm("mov.b64 {%0, %1}, %2;" : "=f"(lo), "=f"(hi) : "l"(v));
}
__device__ __forceinline__ u64 fma2_(u64 a, u64 b, u64 c) {
    u64 d; asm("fma.rn.f32x2 %0, %1, %2, %3;" : "=l"(d) : "l"(a), "l"(b), "l"(c)); return d;
}
__device__ __forceinline__ u64 add2_(u64 a, u64 b) {
    u64 d; asm("add.rn.f32x2 %0, %1, %2;" : "=l"(d) : "l"(a), "l"(b)); return d;
}
__device__ __forceinline__ u64 mul2_(u64 a, u64 b) {
    u64 d; asm("mul.rn.f32x2 %0, %1, %2;" : "=l"(d) : "l"(a), "l"(b)); return d;
}

#define NROWS 38        // rows: image y = y0-3 .. y0+34
#define GSTR  32        // f4 per row (interior arrays)
#define BSTR  34        // f4 stride, border path

// ---------------- interior body (factorized) ----------------
__device__ __forceinline__ void canny_interior(
    const float* __restrict__ im, float* __restrict__ o,
    float g0, float g1, float g2, float g3, float g4,
    int x0, int y0, int W,
    float4* sGX, float4* sGY, int tx, int ty)
{
    const bool le = (tx == 0), re = (tx == 31);

    // composed taps
    const float w0 = g0, w1 = fmaf(2.f, g0, g1),
                w2 = fmaf(2.f, g1, g0 + g2), w3 = fmaf(2.f, g2, g1 + g3);
    const float d2 = g2 - g0;
    const u64 W0 = pk2(w0, w0), W1 = pk2(w1, w1), W2 = pk2(w2, w2), W3 = pk2(w3, w3);
    const u64 D0 = pk2(g0, g0), D1 = pk2(g1, g1), D2 = pk2(d2, d2);
    const u64 N0 = pk2(-g0, -g0), N1 = pk2(-g1, -g1), N2 = pk2(-d2, -d2);

    // ---- stage A: two 7-tap horizontal filters ----
    {
        const int eoff = le ? -4 : 128;
        #pragma unroll
        for (int r = ty; r < NROWS; r += 8) {
            const float* rowp = im + (long)(y0 + r - 3) * W + x0;
            const float4 m4 = *(const float4*)(rowp + 4 * tx);
            float4 e4 = make_float4(0.f, 0.f, 0.f, 0.f);
            if (le | re) e4 = *(const float4*)(rowp + eoff);
            float py = __shfl_up_sync(0xffffffffu, m4.y, 1);
            float pz = __shfl_up_sync(0xffffffffu, m4.z, 1);
            float pw = __shfl_up_sync(0xffffffffu, m4.w, 1);
            float nx = __shfl_down_sync(0xffffffffu, m4.x, 1);
            float ny = __shfl_down_sync(0xffffffffu, m4.y, 1);
            float nz = __shfl_down_sync(0xffffffffu, m4.z, 1);
            if (le) { py = e4.y; pz = e4.z; pw = e4.w; }
            if (re) { nx = e4.x; ny = e4.y; nz = e4.z; }

            const u64 p0 = pk2(py, pz),  p1 = pk2(pz, pw),  p2 = pk2(pw, m4.x);
            const u64 p3 = pk2(m4.x, m4.y), p4 = pk2(m4.y, m4.z), p5 = pk2(m4.z, m4.w);
            const u64 p6 = pk2(m4.w, nx), p7 = pk2(nx, ny), p8 = pk2(ny, nz);

            // hs = corrH(w7): pair0 over p0..p6, pair1 over p2..p8
            u64 s0 = mul2_(W0, p0);
            s0 = fma2_(W1, p1, s0); s0 = fma2_(W2, p2, s0); s0 = fma2_(W3, p3, s0);
            s0 = fma2_(W2, p4, s0); s0 = fma2_(W1, p5, s0); s0 = fma2_(W0, p6, s0);
            u64 s1 = mul2_(W0, p2);
            s1 = fma2_(W1, p3, s1); s1 = fma2_(W2, p4, s1); s1 = fma2_(W3, p5, s1);
            s1 = fma2_(W2, p6, s1); s1 = fma2_(W1, p7, s1); s1 = fma2_(W0, p8, s1);
            // hx = corrH(d7): taps d0,d1,d2,0,-d2,-d1,-d0
            u64 x0p = mul2_(D0, p0);
            x0p = fma2_(D1, p1, x0p); x0p = fma2_(D2, p2, x0p);
            x0p = fma2_(N2, p4, x0p); x0p = fma2_(N1, p5, x0p); x0p = fma2_(N0, p6, x0p);
            u64 x1p = mul2_(D0, p2);
            x1p = fma2_(D1, p3, x1p); x1p = fma2_(D2, p4, x1p);
            x1p = fma2_(N2, p6, x1p); x1p = fma2_(N1, p7, x1p); x1p = fma2_(N0, p8, x1p);

            ulonglong2* gx4 = (ulonglong2*)&sGX[r * GSTR + tx];
            ulonglong2* gy4 = (ulonglong2*)&sGY[r * GSTR + tx];
            *gx4 = make_ulonglong2(x0p, x1p);
            *gy4 = make_ulonglong2(s0, s1);
        }
    }
    __syncthreads();

    // ---- stage B: two vertical 7-tap convolutions, own column only ----
    const int row0 = 4 * ty;
    float* po = o + (long)(y0 + row0) * W + x0 + 4 * tx;

    #pragma unroll
    for (int h = 0; h < 2; h++) {
        u64 ax[2][2], ay[2][2];
        #pragma unroll
        for (int r = 0; r < 2; r++) { ax[r][0] = ax[r][1] = ay[r][0] = ay[r][1] = 0ull; }
        const int rbase = row0 + 2 * h;
        #pragma unroll
        for (int k = 0; k < 8; k++) {
            const ulonglong2 X = *(const ulonglong2*)&sGX[(rbase + k) * GSTR + tx];
            const ulonglong2 Y = *(const ulonglong2*)&sGY[(rbase + k) * GSTR + tx];
            const u64 wt[7] = {W0, W1, W2, W3, W2, W1, W0};
            const u64 dt[7] = {D0, D1, D2, 0ull, N2, N1, N0};
            #pragma unroll
            for (int r = 0; r < 2; r++) {
                const int t = k - r;
                if (t >= 0 && t <= 6) {
                    ax[r][0] = fma2_(wt[t], X.x, ax[r][0]);
                    ax[r][1] = fma2_(wt[t], X.y, ax[r][1]);
                    if (t != 3) {
                        ay[r][0] = fma2_(dt[t], Y.x, ay[r][0]);
                        ay[r][1] = fma2_(dt[t], Y.y, ay[r][1]);
                    }
                }
            }
        }
        #pragma unroll
        for (int r = 0; r < 2; r++) {
            const u64 m0 = fma2_(ay[r][0], ay[r][0], mul2_(ax[r][0], ax[r][0]));
            const u64 m1 = fma2_(ay[r][1], ay[r][1], mul2_(ax[r][1], ax[r][1]));
            float s0, s1, s2, s3;
            upk2(m0, s0, s1); upk2(m1, s2, s3);
            float4 ov;
            ov.x = (s0 < 4.0f) ? 0.0f : s0 * rsqrtf(s0);
            ov.y = (s1 < 4.0f) ? 0.0f : s1 * rsqrtf(s1);
            ov.z = (s2 < 4.0f) ? 0.0f : s2 * rsqrtf(s2);
            ov.w = (s3 < 4.0f) ? 0.0f : s3 * rsqrtf(s3);
            *(float4*)po = ov; po += W;
        }
    }
}

// ---------------- border body (v6, exact zero-pad semantics) ----------------
__device__ __forceinline__ void canny_border(
    const float* __restrict__ im, float* __restrict__ o,
    float g0, float g1, float g2, float g3, float g4,
    int x0, int y0, int W, int H,
    float4* sB, int tx, int ty)
{
    const bool le = (tx == 0), re = (tx == 31);
    {
        const int eoff = le ? -4 : 128;
        const bool eok = (unsigned)(x0 + eoff) < (unsigned)W;
        #pragma unroll
        for (int r = ty; r < NROWS; r += 8) {
            const int gy = y0 + r - 3;
            const float* rowp = im + (long)gy * W + x0;
            float4 m4 = make_float4(0.f, 0.f, 0.f, 0.f);
            float4 e4 = m4;
            const bool rv = (unsigned)gy < (unsigned)H;
            if (rv) {
                m4 = *(const float4*)(rowp + 4 * tx);
                if ((le | re) && eok) e4 = *(const float4*)(rowp + eoff);
            }
            float py = __shfl_up_sync(0xffffffffu, m4.y, 1);
            float pz = __shfl_up_sync(0xffffffffu, m4.z, 1);
            float pw = __shfl_up_sync(0xffffffffu, m4.w, 1);
            float nx = __shfl_down_sync(0xffffffffu, m4.x, 1);
            if (le) { py = e4.y; pz = e4.z; pw = e4.w; }
            if (re) { nx = e4.x; }

            float4 oo;
            oo.x = g0 * py   + g1 * pz   + g2 * pw   + g3 * m4.x + g4 * m4.y;
            oo.y = g0 * pz   + g1 * pw   + g2 * m4.x + g3 * m4.y + g4 * m4.z;
            oo.z = g0 * pw   + g1 * m4.x + g2 * m4.y + g3 * m4.z + g4 * m4.w;
            oo.w = g0 * m4.x + g1 * m4.y + g2 * m4.z + g3 * m4.w + g4 * nx;
            sB[r * BSTR + tx] = oo;

            float hx = g0 * m4.y + g1 * m4.z + g2 * m4.w + g3 * e4.x + g4 * e4.y;
            float hy = g0 * m4.z + g1 * m4.w + g2 * e4.x + g3 * e4.y + g4 * e4.z;
            if (re) { float2 ex = make_float2(hx, hy); *(float2*)&sB[r * BSTR + 32] = ex; }
        }
    }
    __syncthreads();

    const int row0 = 4 * ty;
    u64 pg[5] = {pk2(g0, g0), pk2(g1, g1), pk2(g2, g2), pk2(g3, g3), pk2(g4, g4)};

    u64 aA[6], aB[6], aC[6];
    #pragma unroll
    for (int r = 0; r < 6; r++) { aA[r] = 0ull; aB[r] = 0ull; aC[r] = 0ull; }

    #pragma unroll
    for (int k = 0; k < 10; k++) {
        const float4* rp = &sB[(row0 + k) * BSTR + tx];
        const ulonglong2 AB = *(const ulonglong2*)rp;
        const u64 CC = *(const u64*)(rp + 1);
        #pragma unroll
        for (int br = 0; br < 6; br++) {
            const int ki = k - br;
            if (ki >= 0 && ki < 5) {
                aA[br] = fma2_(pg[ki], AB.x, aA[br]);
                aB[br] = fma2_(pg[ki], AB.y, aB[br]);
                aC[br] = fma2_(pg[ki], CC,   aC[br]);
            }
        }
    }

    if (y0 == 0 || y0 + 32 == H) {
        const int by = y0 + row0 - 1;
        #pragma unroll
        for (int r = 0; r < 6; r++)
            if ((unsigned)(by + r) >= (unsigned)H) { aA[r] = 0ull; aB[r] = 0ull; aC[r] = 0ull; }
    }
    if (x0 == 0 && le) {
        #pragma unroll
        for (int r = 0; r < 6; r++) aA[r] &= 0xFFFFFFFF00000000ull;
    }
    if (x0 + 128 == W && re) {
        #pragma unroll
        for (int r = 0; r < 6; r++) aC[r] &= 0x00000000FFFFFFFFull;
    }

    const u64 TWO2  = pk2(2.f, 2.f);
    const u64 NEG12 = pk2(-1.f, -1.f);
    float* po = o + (long)(y0 + row0) * W + x0 + 4 * tx;

    #define ROW_DS(RI, D1, D2, S1, S2) do {                                   \
        const u64 A_ = aA[RI], B_ = aB[RI], C_ = aC[RI];                      \
        D1 = fma2_(B_, NEG12, A_);                                            \
        D2 = fma2_(C_, NEG12, B_);                                            \
        float a0_, a1_, b0_, b1_, c0_, c1_;                                   \
        upk2(A_, a0_, a1_); upk2(B_, b0_, b1_); upk2(C_, c0_, c1_);           \
        S1 = fma2_(TWO2, pk2(a1_, b0_), add2_(A_, B_));                       \
        S2 = fma2_(TWO2, pk2(b1_, c0_), add2_(B_, C_));                       \
    } while (0)

    #define EMIT(DA1, DA2, DB1, DB2, DC1, DC2, SA1, SA2, SC1, SC2) do {       \
        const u64 gx0 = add2_(DA1, fma2_(TWO2, DB1, DC1));                    \
        const u64 gx1 = add2_(DA2, fma2_(TWO2, DB2, DC2));                    \
        const u64 gy0 = fma2_(SC1, NEG12, SA1);                               \
        const u64 gy1 = fma2_(SC2, NEG12, SA2);                               \
        const u64 m0 = fma2_(gy0, gy0, mul2_(gx0, gx0));                      \
        const u64 m1 = fma2_(gy1, gy1, mul2_(gx1, gx1));                      \
        float s0, s1, s2, s3;                                                 \
        upk2(m0, s0, s1); upk2(m1, s2, s3);                                   \
        float4 ov;                                                            \
        ov.x = (s0 < 4.0f) ? 0.0f : s0 * rsqrtf(s0);                          \
        ov.y = (s1 < 4.0f) ? 0.0f : s1 * rsqrtf(s1);                          \
        ov.z = (s2 < 4.0f) ? 0.0f : s2 * rsqrtf(s2);                          \
        ov.w = (s3 < 4.0f) ? 0.0f : s3 * rsqrtf(s3);                          \
        *(float4*)po = ov; po += W;                                           \
    } while (0)

    u64 d00, d01, s00, s01, d10, d11, s10, s11, d20, d21, s20, s21;
    ROW_DS(0, d00, d01, s00, s01);
    ROW_DS(1, d10, d11, s10, s11);
    ROW_DS(2, d20, d21, s20, s21);
    EMIT(d00, d01, d10, d11, d20, d21, s00, s01, s20, s21);
    ROW_DS(3, d00, d01, s00, s01);
    EMIT(d10, d11, d20, d21, d00, d01, s10, s11, s00, s01);
    ROW_DS(4, d10, d11, s10, s11);
    EMIT(d20, d21, d00, d01, d10, d11, s20, s21, s10, s11);
    ROW_DS(5, d20, d21, s20, s21);
    EMIT(d00, d01, d10, d11, d20, d21, s00, s01, s20, s21);

    #undef ROW_DS
    #undef EMIT
}

__global__ __launch_bounds__(256, 5) void canny_fused_v7(
    const float* __restrict__ img,
    const float* __restrict__ g5,
    float* __restrict__ out,
    int W, int H)
{
    __shared__ __align__(16) char sbuf[NROWS * GSTR * 16 * 2];  // 38912 B

    const int tx = threadIdx.x;
    const int ty = threadIdx.y;
    const int x0 = blockIdx.x * 128;
    const int y0 = blockIdx.y * 32;
    const long plane = (long)W * H;
    const float* im = img + (long)blockIdx.z * plane;
    float* o = out + (long)blockIdx.z * plane;

    const float g0 = __ldg(g5 + 0), g1 = __ldg(g5 + 1), g2 = __ldg(g5 + 2),
                g3 = __ldg(g5 + 3), g4 = __ldg(g5 + 4);

    const bool border = (blockIdx.x == 0) | (blockIdx.x == gridDim.x - 1) |
                        (blockIdx.y == 0) | (blockIdx.y == gridDim.y - 1);
    if (border) {
        canny_border(im, o, g0, g1, g2, g3, g4, x0, y0, W, H, (float4*)sbuf, tx, ty);
    } else {
        float4* sGX = (float4*)sbuf;
        float4* sGY = (float4*)(sbuf + NROWS * GSTR * 16);
        canny_interior(im, o, g0, g1, g2, g3, g4, x0, y0, W, sGX, sGY, tx, ty);
    }
}

extern "C" void kernel_launch(void* const* d_in, const int* in_sizes, int n_in,
                              void* d_out, int out_size) {
    // metadata order: img, gauss_h, gauss_v, sobel_h, sobel_v, dir_w
    const float* img     = (const float*)d_in[0];
    const float* gauss_h = (const float*)d_in[1];
    float* out = (float*)d_out;

    const int W = 1024, H = 1024;
    const int N = in_sizes[0] / (W * H);

    dim3 block(32, 8, 1);
    dim3 grid(W / 128, H / 32, N);
    canny_fused_v7<<<grid, block>>>(img, gauss_h, out, W, H);
}

// round 14
// speedup vs baseline: 1.0097x; 1.0097x over previous
#include <cuda_runtime.h>

// Fused Canny front-end (separable 5-tap Gaussian + Sobel + magnitude threshold).
// Reference's NMS/orientation path is dead code w.r.t. the returned tensor.
//
// v8 = v6 (best) + two issue-count cuts:
//   - tile-edge hgauss pair computed by a dedicated 38-thread pass (was 10 FMA
//     per iteration on ALL lanes in stage A's main loop)
//   - sqrt.approx.f32 (1 MUFU) instead of rsqrtf+mul
// Stage-A hgauss grid shifted by -1 col so stage B reads its 6 blurred columns
// as three ALIGNED 64-bit pairs (LDS.128 + LDS.64): A=(x-1,x) B=(x+1,x+2) C=(x+3,x+4).
// Boundary: reference zero-pads the *blurred* tensor before Sobel -> masked
// (y: row zeroing; x: 64-bit AND on edge lanes), border CTAs only.

typedef unsigned long long u64;

__device__ __forceinline__ u64 pk2(float lo, float hi) {
    u64 r; asm("mov.b64 %0, {%1, %2};" : "=l"(r) : "f"(lo), "f"(hi)); return r;
}
__device__ __forceinline__ void upk2(u64 v, float& lo, float& hi) {
    asm("mov.b64 {%0, %1}, %2;" : "=f"(lo), "=f"(hi) : "l"(v));
}
__device__ __forceinline__ u64 fma2_(u64 a, u64 b, u64 c) {
    u64 d; asm("fma.rn.f32x2 %0, %1, %2, %3;" : "=l"(d) : "l"(a), "l"(b), "l"(c)); return d;
}
__device__ __forceinline__ u64 add2_(u64 a, u64 b) {
    u64 d; asm("add.rn.f32x2 %0, %1, %2;" : "=l"(d) : "l"(a), "l"(b)); return d;
}
__device__ __forceinline__ u64 mul2_(u64 a, u64 b) {
    u64 d; asm("mul.rn.f32x2 %0, %1, %2;" : "=l"(d) : "l"(a), "l"(b)); return d;
}
__device__ __forceinline__ float sqrt_ap(float x) {
    float r; asm("sqrt.approx.f32 %0, %1;" : "=f"(r) : "f"(x)); return r;
}

#define NROWS 38        // sB rows: image y = y0-3 .. y0+34
#define BSTR  34        // f4 stride per row (33 used + pad)

template<bool BORDER>
__device__ __forceinline__ void canny_body(
    const float* __restrict__ im, float* __restrict__ o,
    float g0, float g1, float g2, float g3, float g4,
    int x0, int y0, int W, int H,
    float4* sB, int tx, int ty, int t)
{
    const bool le = (tx == 0), re = (tx == 31);

    // ---- stage A: coalesced load + SHIFTED horizontal gaussian ----
    // sB[r][tx] = hgauss at cols (x-1, x, x+1, x+2), x = x0+4tx.
    {
        const int eoff = le ? -4 : 128;
        const bool eok = !BORDER || ((unsigned)(x0 + eoff) < (unsigned)W);
        #pragma unroll
        for (int r = ty; r < NROWS; r += 8) {
            const int gy = y0 + r - 3;
            const float* rowp = im + (long)gy * W + x0;
            float4 m4 = make_float4(0.f, 0.f, 0.f, 0.f);
            float4 e4 = m4;
            if (!BORDER) {
                m4 = *(const float4*)(rowp + 4 * tx);
                if (le | re) e4 = *(const float4*)(rowp + eoff);
            } else {
                const bool rv = (unsigned)gy < (unsigned)H;
                if (rv) {
                    m4 = *(const float4*)(rowp + 4 * tx);
                    if ((le | re) && eok) e4 = *(const float4*)(rowp + eoff);
                }
            }
            // halo raw floats: py,pz,pw = in[x-3..x-1]; nx = in[x+4]
            float py = __shfl_up_sync(0xffffffffu, m4.y, 1);
            float pz = __shfl_up_sync(0xffffffffu, m4.z, 1);
            float pw = __shfl_up_sync(0xffffffffu, m4.w, 1);
            float nx = __shfl_down_sync(0xffffffffu, m4.x, 1);
            if (le) { py = e4.y; pz = e4.z; pw = e4.w; }
            if (re) { nx = e4.x; }

            float4 oo;
            oo.x = g0 * py   + g1 * pz   + g2 * pw   + g3 * m4.x + g4 * m4.y;  // x-1
            oo.y = g0 * pz   + g1 * pw   + g2 * m4.x + g3 * m4.y + g4 * m4.z;  // x
            oo.z = g0 * pw   + g1 * m4.x + g2 * m4.y + g3 * m4.z + g4 * m4.w;  // x+1
            oo.w = g0 * m4.x + g1 * m4.y + g2 * m4.z + g3 * m4.w + g4 * nx;    // x+2
            sB[r * BSTR + tx] = oo;
        }
    }

    // ---- stage A': tile-edge hgauss pair (h(x0+127), h(x0+128)) -> sB[r][32].xy
    // One thread per row; reads in[x0+125 .. x0+130].
    if (t < NROWS) {
        const int r = t;
        const int gy = y0 + r - 3;
        float a = 0.f, b = 0.f, c = 0.f, d = 0.f, e = 0.f, f = 0.f;
        if (!BORDER) {
            const float* p = im + (long)gy * W + (x0 + 125);
            a = p[0]; b = p[1]; c = p[2]; d = p[3]; e = p[4]; f = p[5];
        } else if ((unsigned)gy < (unsigned)H) {
            const float* p = im + (long)gy * W;
            const int xb = x0 + 125;
            if ((unsigned)(xb + 0) < (unsigned)W) a = p[xb + 0];
            if ((unsigned)(xb + 1) < (unsigned)W) b = p[xb + 1];
            if ((unsigned)(xb + 2) < (unsigned)W) c = p[xb + 2];
            if ((unsigned)(xb + 3) < (unsigned)W) d = p[xb + 3];
            if ((unsigned)(xb + 4) < (unsigned)W) e = p[xb + 4];
            if ((unsigned)(xb + 5) < (unsigned)W) f = p[xb + 5];
        }
        float2 ex;
        ex.x = g0 * a + g1 * b + g2 * c + g3 * d + g4 * e;   // h(x0+127)
        ex.y = g0 * b + g1 * c + g2 * d + g3 * e + g4 * f;   // h(x0+128)
        *(float2*)&sB[r * BSTR + 32] = ex;
    }
    __syncthreads();

    // ---- stage B: vertical gaussian on aligned pairs -> rolling sobel ----
    const int row0 = 4 * ty;
    u64 pg[5] = {pk2(g0, g0), pk2(g1, g1), pk2(g2, g2), pk2(g3, g3), pk2(g4, g4)};

    u64 aA[6], aB[6], aC[6];
    #pragma unroll
    for (int r = 0; r < 6; r++) { aA[r] = 0ull; aB[r] = 0ull; aC[r] = 0ull; }

    #pragma unroll
    for (int k = 0; k < 10; k++) {
        const float4* rp = &sB[(row0 + k) * BSTR + tx];
        const ulonglong2 AB = *(const ulonglong2*)rp;     // (c0,c1),(c2,c3)
        const u64 CC = *(const u64*)(rp + 1);             // (c4,c5)
        #pragma unroll
        for (int br = 0; br < 6; br++) {
            const int ki = k - br;
            if (ki >= 0 && ki < 5) {
                aA[br] = fma2_(pg[ki], AB.x, aA[br]);
                aB[br] = fma2_(pg[ki], AB.y, aB[br]);
                aC[br] = fma2_(pg[ki], CC,   aC[br]);
            }
        }
    }

    if (BORDER) {
        // y-mask: blurred rows outside image -> 0
        if (y0 == 0 || y0 + 32 == H) {
            const int by = y0 + row0 - 1;
            #pragma unroll
            for (int r = 0; r < 6; r++)
                if ((unsigned)(by + r) >= (unsigned)H) { aA[r] = 0ull; aB[r] = 0ull; aC[r] = 0ull; }
        }
        // x-mask: blurred col x0-1 (A.lo, lane 0) / x0+128 (C.hi, lane 31) -> 0
        if (x0 == 0 && le) {
            #pragma unroll
            for (int r = 0; r < 6; r++) aA[r] &= 0xFFFFFFFF00000000ull;
        }
        if (x0 + 128 == W && re) {
            #pragma unroll
            for (int r = 0; r < 6; r++) aC[r] &= 0x00000000FFFFFFFFull;
        }
    }

    const u64 TWO2  = pk2(2.f, 2.f);
    const u64 NEG12 = pk2(-1.f, -1.f);
    float* po = o + (long)(y0 + row0) * W + x0 + 4 * tx;

    #define ROW_DS(RI, D1, D2, S1, S2) do {                                   \
        const u64 A_ = aA[RI], B_ = aB[RI], C_ = aC[RI];                      \
        D1 = fma2_(B_, NEG12, A_);                                            \
        D2 = fma2_(C_, NEG12, B_);                                            \
        float a0_, a1_, b0_, b1_, c0_, c1_;                                   \
        upk2(A_, a0_, a1_); upk2(B_, b0_, b1_); upk2(C_, c0_, c1_);           \
        S1 = fma2_(TWO2, pk2(a1_, b0_), add2_(A_, B_));                       \
        S2 = fma2_(TWO2, pk2(b1_, c0_), add2_(B_, C_));                       \
    } while (0)

    #define EMIT(DA1, DA2, DB1, DB2, DC1, DC2, SA1, SA2, SC1, SC2) do {       \
        const u64 gx0 = add2_(DA1, fma2_(TWO2, DB1, DC1));                    \
        const u64 gx1 = add2_(DA2, fma2_(TWO2, DB2, DC2));                    \
        const u64 gy0 = fma2_(SC1, NEG12, SA1);                               \
        const u64 gy1 = fma2_(SC2, NEG12, SA2);                               \
        const u64 m0 = fma2_(gy0, gy0, mul2_(gx0, gx0));                      \
        const u64 m1 = fma2_(gy1, gy1, mul2_(gx1, gx1));                      \
        float s0, s1, s2, s3;                                                 \
        upk2(m0, s0, s1); upk2(m1, s2, s3);                                   \
        float4 ov;                                                            \
        ov.x = (s0 < 4.0f) ? 0.0f : sqrt_ap(s0);                              \
        ov.y = (s1 < 4.0f) ? 0.0f : sqrt_ap(s1);                              \
        ov.z = (s2 < 4.0f) ? 0.0f : sqrt_ap(s2);                              \
        ov.w = (s3 < 4.0f) ? 0.0f : sqrt_ap(s3);                              \
        *(float4*)po = ov; po += W;                                           \
    } while (0)

    u64 d00, d01, s00, s01, d10, d11, s10, s11, d20, d21, s20, s21;
    ROW_DS(0, d00, d01, s00, s01);
    ROW_DS(1, d10, d11, s10, s11);
    ROW_DS(2, d20, d21, s20, s21);
    EMIT(d00, d01, d10, d11, d20, d21, s00, s01, s20, s21);
    ROW_DS(3, d00, d01, s00, s01);
    EMIT(d10, d11, d20, d21, d00, d01, s10, s11, s00, s01);
    ROW_DS(4, d10, d11, s10, s11);
    EMIT(d20, d21, d00, d01, d10, d11, s20, s21, s10, s11);
    ROW_DS(5, d20, d21, s20, s21);
    EMIT(d00, d01, d10, d11, d20, d21, s00, s01, s20, s21);

    #undef ROW_DS
    #undef EMIT
}

__global__ __launch_bounds__(256, 5) void canny_fused_v8(
    const float* __restrict__ img,
    const float* __restrict__ g5,
    float* __restrict__ out,
    int W, int H)
{
    __shared__ float4 sB[NROWS * BSTR];   // 20672 B

    const int tx = threadIdx.x;
    const int ty = threadIdx.y;
    const int t  = ty * 32 + tx;
    const int x0 = blockIdx.x * 128;
    const int y0 = blockIdx.y * 32;
    const long plane = (long)W * H;
    const float* im = img + (long)blockIdx.z * plane;
    float* o = out + (long)blockIdx.z * plane;

    const float g0 = __ldg(g5 + 0), g1 = __ldg(g5 + 1), g2 = __ldg(g5 + 2),
                g3 = __ldg(g5 + 3), g4 = __ldg(g5 + 4);

    const bool border = (blockIdx.x == 0) | (blockIdx.x == gridDim.x - 1) |
                        (blockIdx.y == 0) | (blockIdx.y == gridDim.y - 1);
    if (border)
        canny_body<true >(im, o, g0, g1, g2, g3, g4, x0, y0, W, H, sB, tx, ty, t);
    else
        canny_body<false>(im, o, g0, g1, g2, g3, g4, x0, y0, W, H, sB, tx, ty, t);
}

extern "C" void kernel_launch(void* const* d_in, const int* in_sizes, int n_in,
                              void* d_out, int out_size) {
    // metadata order: img, gauss_h, gauss_v, sobel_h, sobel_v, dir_w
    const float* img     = (const float*)d_in[0];
    const float* gauss_h = (const float*)d_in[1];
    float* out = (float*)d_out;

    const int W = 1024, H = 1024;
    const int N = in_sizes[0] / (W * H);

    dim3 block(32, 8, 1);
    dim3 grid(W / 128, H / 32, N);
    canny_fused_v8<<<grid, block>>>(img, gauss_h, out, W, H);
}